// round 13
// baseline (speedup 1.0000x reference)
#include <cuda_runtime.h>

// FFT long conv, N = 16384 = 4^7, one CTA per row.
// R13 = R9 (best, 350.7us) + divergence-free fused_mid with FORCED no-unroll
// (#pragma unroll 1). R11/R12 post-mortem: fully unrolling fused_mid's 4-item
// loop put 4x32 regs of live state in flight -> 128 regs + local spills
// (L1% was LDL/STL). One iteration at a time keeps regs at R9 levels.

#define L_SIG  8192
#define N_FFT  16384
#define NT     512
#define SMEM_F2 (N_FFT + (N_FFT >> 4))     // 17408 float2
#define SMEM_BYTES (SMEM_F2 * 8)           // 139264 B

__device__ __forceinline__ int SKEW(int i) { return i + (i >> 4); }

__device__ __forceinline__ float2 cadd(float2 a, float2 b) { return make_float2(a.x + b.x, a.y + b.y); }
__device__ __forceinline__ float2 csub(float2 a, float2 b) { return make_float2(a.x - b.x, a.y - b.y); }
__device__ __forceinline__ float2 cmul(float2 a, float2 b) {
    return make_float2(fmaf(a.x, b.x, -a.y * b.y), fmaf(a.x, b.y, a.y * b.x));
}
__device__ __forceinline__ float2 cconj(float2 a) { return make_float2(a.x, -a.y); }

// reverse six base-4 digits of a 12-bit value
__device__ __forceinline__ int rev6_base4(int c) {
    unsigned r = __brev((unsigned)c) >> 20;
    return (int)(((r & 0xAAAu) >> 1) | ((r & 0x555u) << 1));
}

__device__ __forceinline__ void dft4_fwd(float2& a0, float2& a1, float2& a2, float2& a3) {
    float2 t0 = cadd(a0, a2), t1 = csub(a0, a2), t2 = cadd(a1, a3), t3 = csub(a1, a3);
    a0 = cadd(t0, t2); a2 = csub(t0, t2);
    a1 = make_float2(t1.x + t3.y, t1.y - t3.x);   // t1 - i*t3
    a3 = make_float2(t1.x - t3.y, t1.y + t3.x);   // t1 + i*t3
}
__device__ __forceinline__ void dft4_inv(float2& a0, float2& a1, float2& a2, float2& a3) {
    float2 t0 = cadd(a0, a2), t1 = csub(a0, a2), t2 = cadd(a1, a3), t3 = csub(a1, a3);
    a0 = cadd(t0, t2); a2 = csub(t0, t2);
    a1 = make_float2(t1.x - t3.y, t1.y + t3.x);   // t1 + i*t3
    a3 = make_float2(t1.x + t3.y, t1.y - t3.x);   // t1 - i*t3
}

// omega16^k = e^{-+ 2*pi*i*k/16}; k compile-time after unroll (k in {0..9})
__device__ __forceinline__ float2 om16(int k, bool inv) {
    const float OC[10] = {1.f, 0.9238795325f, 0.7071067812f, 0.3826834324f, 0.f,
                          0.f, -0.7071067812f, 0.f, 0.f, -0.9238795325f};
    const float OS[10] = {0.f, 0.3826834324f, 0.7071067812f, 0.9238795325f, 1.f,
                          0.f, 0.7071067812f, 0.f, 0.f, -0.3826834324f};
    return make_float2(OC[k], inv ? OS[k] : -OS[k]);
}

// ---- fused forward pass, S=1024, reads x,h from gmem (upper half implicit zero) ----
__device__ __forceinline__ void pass1_fused(float2* z, const float* __restrict__ xr,
                                            const float* __restrict__ hr, int tid) {
    const float tstep = -6.2831853071795864f / 16384.0f;
    #pragma unroll
    for (int it = 0; it < 2; it++) {
        const int j = tid + it * NT;

        float2 in[8];
        #pragma unroll
        for (int r = 0; r < 8; r++)
            in[r] = make_float2(xr[j + 1024 * r], hr[j + 1024 * r]);

        float sn, cs;
        __sincosf(tstep * (float)j, &sn, &cs);
        const float2 W   = make_float2(cs, sn);
        const float2 W2  = cmul(W, W);
        const float2 W3  = cmul(W2, W);
        const float2 W4  = cmul(W2, W2);
        const float2 W8  = cmul(W4, W4);
        const float2 W12 = cmul(W8, W4);

        float2 b[16];
        #pragma unroll
        for (int r0 = 0; r0 < 4; r0++) {         // level m = 4096, a2=a3=0
            float2 a0 = in[r0], a1 = in[r0 + 4];
            float2 y0 = cadd(a0, a1);
            float2 y2 = csub(a0, a1);
            float2 y1 = make_float2(a0.x + a1.y, a0.y - a1.x);  // a0 - i*a1
            float2 y3 = make_float2(a0.x - a1.y, a0.y + a1.x);  // a0 + i*a1
            b[r0]      = y0;
            b[r0 + 4]  = cmul(y1, r0 ? cmul(W,  om16(r0,     false)) : W);
            b[r0 + 8]  = cmul(y2, r0 ? cmul(W2, om16(2 * r0, false)) : W2);
            b[r0 + 12] = cmul(y3, r0 ? cmul(W3, om16(3 * r0, false)) : W3);
        }
        #pragma unroll
        for (int d = 0; d < 4; d++) {            // level m = 1024
            float2 a0 = b[4*d], a1 = b[4*d+1], a2 = b[4*d+2], a3 = b[4*d+3];
            dft4_fwd(a0, a1, a2, a3);
            b[4*d]   = a0;
            b[4*d+1] = cmul(a1, W4);
            b[4*d+2] = cmul(a2, W8);
            b[4*d+3] = cmul(a3, W12);
        }
        #pragma unroll
        for (int r = 0; r < 16; r++) z[SKEW(j + 1024 * r)] = b[r];
    }
}

// ---- fused inverse pass, S=1024, writes Re(outputs 0..8191)*scale to gmem ----
__device__ __forceinline__ void pass7_fused(const float2* z, float* __restrict__ yr, int tid) {
    const float tstep = 6.2831853071795864f / 16384.0f;
    const float scale = 1.0f / (16384.0f * 16384.0f);
    #pragma unroll
    for (int it = 0; it < 2; it++) {
        const int j = tid + it * NT;

        float2 b[16];
        #pragma unroll
        for (int r = 0; r < 16; r++) b[r] = z[SKEW(j + 1024 * r)];

        float sn, cs;
        __sincosf(tstep * (float)j, &sn, &cs);
        const float2 W   = make_float2(cs, sn);
        const float2 W2  = cmul(W, W);
        const float2 W3  = cmul(W2, W);
        const float2 W4  = cmul(W2, W2);
        const float2 W8  = cmul(W4, W4);
        const float2 W12 = cmul(W8, W4);

        #pragma unroll
        for (int d = 0; d < 4; d++) {            // level m = 1024 (full complex)
            float2 a0 = b[4*d];
            float2 a1 = cmul(b[4*d+1], W4);
            float2 a2 = cmul(b[4*d+2], W8);
            float2 a3 = cmul(b[4*d+3], W12);
            dft4_inv(a0, a1, a2, a3);
            b[4*d] = a0; b[4*d+1] = a1; b[4*d+2] = a2; b[4*d+3] = a3;
        }
        #pragma unroll
        for (int r0 = 0; r0 < 4; r0++) {         // level m = 4096: Re of outs 0..7 only
            float2 in0 = b[r0];
            float2 in1 = cmul(b[r0 + 4],  r0 ? cmul(W,  om16(r0,     true)) : W);
            float  in2x;
            {
                float2 w = r0 ? cmul(W2, om16(2 * r0, true)) : W2;
                float2 v = b[r0 + 8];
                in2x = fmaf(v.x, w.x, -v.y * w.y);      // Re(v * w)
            }
            float2 in3 = cmul(b[r0 + 12], r0 ? cmul(W3, om16(3 * r0, true)) : W3);
            float re0 = (in0.x + in2x) + (in1.x + in3.x);   // Re(out[r0])
            float re1 = (in0.x - in2x) - (in1.y - in3.y);   // Re(out[r0+4])
            yr[j + 1024 * r0]       = re0 * scale;
            yr[j + 1024 * (r0 + 4)] = re1 * scale;
        }
    }
}

// ---- generic radix-16 pass (middle passes: S=64, S=4), sincosf twiddles ----
template<int S, bool INV>
__device__ __forceinline__ void radix16_pass(float2* z, int tid) {
    const float ang0 = (INV ? 6.2831853071795864f : -6.2831853071795864f) / (16.0f * (float)S);
    #pragma unroll
    for (int it = 0; it < (N_FFT / 16) / NT; it++) {
        const int idx = tid + it * NT;
        const int j = idx & (S - 1);
        const int base = (idx / S) * (16 * S) + j;

        float2 b[16];
        #pragma unroll
        for (int r = 0; r < 16; r++) b[r] = z[SKEW(base + S * r)];

        float sn, cs;
        __sincosf(ang0 * (float)j, &sn, &cs);
        const float2 W   = make_float2(cs, sn);
        const float2 W2  = cmul(W, W);
        const float2 W3  = cmul(W2, W);
        const float2 W4  = cmul(W2, W2);
        const float2 W8  = cmul(W4, W4);
        const float2 W12 = cmul(W8, W4);

        if (!INV) {
            #pragma unroll
            for (int r0 = 0; r0 < 4; r0++) {     // level m = 4S
                float2 a0 = b[r0], a1 = b[r0 + 4], a2 = b[r0 + 8], a3 = b[r0 + 12];
                dft4_fwd(a0, a1, a2, a3);
                b[r0]      = a0;
                b[r0 + 4]  = cmul(a1, r0 ? cmul(W,  om16(r0,     false)) : W);
                b[r0 + 8]  = cmul(a2, r0 ? cmul(W2, om16(2 * r0, false)) : W2);
                b[r0 + 12] = cmul(a3, r0 ? cmul(W3, om16(3 * r0, false)) : W3);
            }
            #pragma unroll
            for (int d = 0; d < 4; d++) {        // level m = S
                float2 a0 = b[4*d], a1 = b[4*d+1], a2 = b[4*d+2], a3 = b[4*d+3];
                dft4_fwd(a0, a1, a2, a3);
                b[4*d]   = a0;
                b[4*d+1] = cmul(a1, W4);
                b[4*d+2] = cmul(a2, W8);
                b[4*d+3] = cmul(a3, W12);
            }
        } else {
            #pragma unroll
            for (int d = 0; d < 4; d++) {        // level m = S
                float2 a0 = b[4*d];
                float2 a1 = cmul(b[4*d+1], W4);
                float2 a2 = cmul(b[4*d+2], W8);
                float2 a3 = cmul(b[4*d+3], W12);
                dft4_inv(a0, a1, a2, a3);
                b[4*d] = a0; b[4*d+1] = a1; b[4*d+2] = a2; b[4*d+3] = a3;
            }
            #pragma unroll
            for (int r0 = 0; r0 < 4; r0++) {     // level m = 4S
                float2 a0 = b[r0];
                float2 a1 = cmul(b[r0 + 4],  r0 ? cmul(W,  om16(r0,     true)) : W);
                float2 a2 = cmul(b[r0 + 8],  r0 ? cmul(W2, om16(2 * r0, true)) : W2);
                float2 a3 = cmul(b[r0 + 12], r0 ? cmul(W3, om16(3 * r0, true)) : W3);
                dft4_inv(a0, a1, a2, a3);
                b[r0] = a0; b[r0 + 4] = a1; b[r0 + 8] = a2; b[r0 + 12] = a3;
            }
        }

        #pragma unroll
        for (int r = 0; r < 16; r++) z[SKEW(base + S * r)] = b[r];
    }
}

// ---- fused middle: fwd radix-4 (m=1) + combine + inv radix-4 (m=1) ----
// Divergence-free frequency iteration, but NOT unrolled (unroll 1): one
// iteration's registers live at a time. k0=2048: c==cp, duplicate-identical
// writes (benign).
__device__ __forceinline__ void fused_mid(float2* z, int tid) {
    if (tid == 0) {
        float2 A0 = z[SKEW(0)], A1 = z[SKEW(1)], A2 = z[SKEW(2)], A3 = z[SKEW(3)];
        dft4_fwd(A0, A1, A2, A3);                // freqs 0, 4096, 8192, 12288
        float2 Y0 = make_float2(A0.x * A0.y, 0.0f);        // DC: both real
        float2 Y2 = make_float2(A2.x * A2.y, 0.0f);        // Nyquist: both real
        float2 Za = A1, Zb = A3;                           // 4096 <-> 12288
        float2 X = make_float2(0.5f * (Za.x + Zb.x), 0.5f * (Za.y - Zb.y));
        float2 H = make_float2(0.5f * (Za.y + Zb.y), 0.5f * (Zb.x - Za.x));
        float2 Y1 = cmul(X, H);
        float2 Y3 = cconj(Y1);
        dft4_inv(Y0, Y1, Y2, Y3);
        z[SKEW(0)] = Y0; z[SKEW(1)] = Y1; z[SKEW(2)] = Y2; z[SKEW(3)] = Y3;
    }
    #pragma unroll 1
    for (int q = 0; q < 4; q++) {
        const int k0 = 1 + tid + q * NT;         // 1..2048
        const int c  = rev6_base4(k0);
        const int cp = rev6_base4(4096 - k0);

        float2 A[4], B[4];
        #pragma unroll
        for (int t = 0; t < 4; t++) A[t] = z[SKEW(4 * c + t)];
        #pragma unroll
        for (int t = 0; t < 4; t++) B[t] = z[SKEW(4 * cp + t)];

        dft4_fwd(A[0], A[1], A[2], A[3]);
        dft4_fwd(B[0], B[1], B[2], B[3]);

        float2 An[4], Bn[4];
        #pragma unroll
        for (int t = 0; t < 4; t++) {
            float2 Za = A[t], Zb = B[3 - t];
            float2 X = make_float2(0.5f * (Za.x + Zb.x), 0.5f * (Za.y - Zb.y));
            float2 H = make_float2(0.5f * (Za.y + Zb.y), 0.5f * (Zb.x - Za.x));
            float2 Y = cmul(X, H);
            An[t] = Y;
            Bn[3 - t] = cconj(Y);
        }

        dft4_inv(An[0], An[1], An[2], An[3]);
        dft4_inv(Bn[0], Bn[1], Bn[2], Bn[3]);

        #pragma unroll
        for (int t = 0; t < 4; t++) z[SKEW(4 * c + t)] = An[t];
        #pragma unroll
        for (int t = 0; t < 4; t++) z[SKEW(4 * cp + t)] = Bn[t];
    }
}

__global__ __launch_bounds__(NT, 1)
void fftconv_kernel(const float* __restrict__ x, const float* __restrict__ h,
                    float* __restrict__ y) {
    extern __shared__ float2 z[];
    const int row = blockIdx.x;
    const int tid = threadIdx.x;
    const float* xr = x + (size_t)row * L_SIG;
    const float* hr = h + (size_t)row * L_SIG;
    float* yr = y + (size_t)row * L_SIG;

    pass1_fused(z, xr, hr, tid);       __syncthreads();
    radix16_pass<64, false>(z, tid);   __syncthreads();
    radix16_pass<4,  false>(z, tid);   __syncthreads();
    fused_mid(z, tid);                 __syncthreads();
    radix16_pass<4,  true >(z, tid);   __syncthreads();
    radix16_pass<64, true >(z, tid);   __syncthreads();
    pass7_fused(z, yr, tid);
}

extern "C" void kernel_launch(void* const* d_in, const int* in_sizes, int n_in,
                              void* d_out, int out_size) {
    const float* x = (const float*)d_in[0];
    const float* h = (const float*)d_in[1];
    float* y = (float*)d_out;

    cudaFuncSetAttribute(fftconv_kernel,
                         cudaFuncAttributeMaxDynamicSharedMemorySize, SMEM_BYTES);

    const int B = in_sizes[0] / L_SIG;   // 4096 rows
    fftconv_kernel<<<B, NT, SMEM_BYTES>>>(x, h, y);
}

// round 14
// speedup vs baseline: 2.0256x; 2.0256x over previous
#include <cuda_runtime.h>

// FFT long conv, N = 16384 = 4^7, one CTA per row.
// R14 = R9 arithmetic (best, 350.7us) with LDS.128 pairing:
//   thread t handles ADJACENT butterflies (2t, 2t+1) -> all SMEM traffic is
//   float4 (half the LDS/STS issues + half the address ALU vs R9's LDS.64).
//   Skew = i + 2*(i>>5): keeps even pairs adjacent, 16B-aligned, and
//   conflict-free per-phase for S=1024/64/4 (hand-checked quad-bank map).
// fused_mid is R9's verbatim divergent version (R11-R13 all showed any rework
// of it -> 128 regs + local spills -> 2x slowdown).

#define L_SIG  8192
#define N_FFT  16384
#define NT     512
#define SMEM_F2 (N_FFT + 2 * (N_FFT >> 5))   // 17408 float2
#define SMEM_BYTES (SMEM_F2 * 8)             // 139264 B

__device__ __forceinline__ int SKEW(int i) { return i + 2 * (i >> 5); }

__device__ __forceinline__ float2 cadd(float2 a, float2 b) { return make_float2(a.x + b.x, a.y + b.y); }
__device__ __forceinline__ float2 csub(float2 a, float2 b) { return make_float2(a.x - b.x, a.y - b.y); }
__device__ __forceinline__ float2 cmul(float2 a, float2 b) {
    return make_float2(fmaf(a.x, b.x, -a.y * b.y), fmaf(a.x, b.y, a.y * b.x));
}
__device__ __forceinline__ float2 cconj(float2 a) { return make_float2(a.x, -a.y); }

// reverse six base-4 digits of a 12-bit value
__device__ __forceinline__ int rev6_base4(int c) {
    unsigned r = __brev((unsigned)c) >> 20;
    return (int)(((r & 0xAAAu) >> 1) | ((r & 0x555u) << 1));
}

__device__ __forceinline__ void dft4_fwd(float2& a0, float2& a1, float2& a2, float2& a3) {
    float2 t0 = cadd(a0, a2), t1 = csub(a0, a2), t2 = cadd(a1, a3), t3 = csub(a1, a3);
    a0 = cadd(t0, t2); a2 = csub(t0, t2);
    a1 = make_float2(t1.x + t3.y, t1.y - t3.x);   // t1 - i*t3
    a3 = make_float2(t1.x - t3.y, t1.y + t3.x);   // t1 + i*t3
}
__device__ __forceinline__ void dft4_inv(float2& a0, float2& a1, float2& a2, float2& a3) {
    float2 t0 = cadd(a0, a2), t1 = csub(a0, a2), t2 = cadd(a1, a3), t3 = csub(a1, a3);
    a0 = cadd(t0, t2); a2 = csub(t0, t2);
    a1 = make_float2(t1.x - t3.y, t1.y + t3.x);   // t1 + i*t3
    a3 = make_float2(t1.x + t3.y, t1.y - t3.x);   // t1 - i*t3
}

// omega16^k = e^{-+ 2*pi*i*k/16}; k compile-time after unroll (k in {0..9})
__device__ __forceinline__ float2 om16(int k, bool inv) {
    const float OC[10] = {1.f, 0.9238795325f, 0.7071067812f, 0.3826834324f, 0.f,
                          0.f, -0.7071067812f, 0.f, 0.f, -0.9238795325f};
    const float OS[10] = {0.f, 0.3826834324f, 0.7071067812f, 0.9238795325f, 1.f,
                          0.f, 0.7071067812f, 0.f, 0.f, -0.3826834324f};
    return make_float2(OC[k], inv ? OS[k] : -OS[k]);
}

// Full radix-16 butterfly on b[16] with base twiddle W (same op order as R9).
template<bool INV>
__device__ __forceinline__ void bfly16(float2* b, float2 W) {
    const float2 W2  = cmul(W, W);
    const float2 W3  = cmul(W2, W);
    const float2 W4  = cmul(W2, W2);
    const float2 W8  = cmul(W4, W4);
    const float2 W12 = cmul(W8, W4);
    if (!INV) {
        #pragma unroll
        for (int r0 = 0; r0 < 4; r0++) {         // level m = 4S
            float2 a0 = b[r0], a1 = b[r0 + 4], a2 = b[r0 + 8], a3 = b[r0 + 12];
            dft4_fwd(a0, a1, a2, a3);
            b[r0]      = a0;
            b[r0 + 4]  = cmul(a1, r0 ? cmul(W,  om16(r0,     false)) : W);
            b[r0 + 8]  = cmul(a2, r0 ? cmul(W2, om16(2 * r0, false)) : W2);
            b[r0 + 12] = cmul(a3, r0 ? cmul(W3, om16(3 * r0, false)) : W3);
        }
        #pragma unroll
        for (int d = 0; d < 4; d++) {            // level m = S
            float2 a0 = b[4*d], a1 = b[4*d+1], a2 = b[4*d+2], a3 = b[4*d+3];
            dft4_fwd(a0, a1, a2, a3);
            b[4*d]   = a0;
            b[4*d+1] = cmul(a1, W4);
            b[4*d+2] = cmul(a2, W8);
            b[4*d+3] = cmul(a3, W12);
        }
    } else {
        #pragma unroll
        for (int d = 0; d < 4; d++) {            // level m = S
            float2 a0 = b[4*d];
            float2 a1 = cmul(b[4*d+1], W4);
            float2 a2 = cmul(b[4*d+2], W8);
            float2 a3 = cmul(b[4*d+3], W12);
            dft4_inv(a0, a1, a2, a3);
            b[4*d] = a0; b[4*d+1] = a1; b[4*d+2] = a2; b[4*d+3] = a3;
        }
        #pragma unroll
        for (int r0 = 0; r0 < 4; r0++) {         // level m = 4S
            float2 a0 = b[r0];
            float2 a1 = cmul(b[r0 + 4],  r0 ? cmul(W,  om16(r0,     true)) : W);
            float2 a2 = cmul(b[r0 + 8],  r0 ? cmul(W2, om16(2 * r0, true)) : W2);
            float2 a3 = cmul(b[r0 + 12], r0 ? cmul(W3, om16(3 * r0, true)) : W3);
            dft4_inv(a0, a1, a2, a3);
            b[r0] = a0; b[r0 + 4] = a1; b[r0 + 8] = a2; b[r0 + 12] = a3;
        }
    }
}

// First-pass butterfly: inputs in[8] (upper half of FFT implicitly zero).
__device__ __forceinline__ void bfly16_first(const float2* in, float2* b, float2 W) {
    const float2 W2  = cmul(W, W);
    const float2 W3  = cmul(W2, W);
    const float2 W4  = cmul(W2, W2);
    const float2 W8  = cmul(W4, W4);
    const float2 W12 = cmul(W8, W4);
    #pragma unroll
    for (int r0 = 0; r0 < 4; r0++) {             // level m = 4096, a2=a3=0
        float2 a0 = in[r0], a1 = in[r0 + 4];
        float2 y0 = cadd(a0, a1);
        float2 y2 = csub(a0, a1);
        float2 y1 = make_float2(a0.x + a1.y, a0.y - a1.x);  // a0 - i*a1
        float2 y3 = make_float2(a0.x - a1.y, a0.y + a1.x);  // a0 + i*a1
        b[r0]      = y0;
        b[r0 + 4]  = cmul(y1, r0 ? cmul(W,  om16(r0,     false)) : W);
        b[r0 + 8]  = cmul(y2, r0 ? cmul(W2, om16(2 * r0, false)) : W2);
        b[r0 + 12] = cmul(y3, r0 ? cmul(W3, om16(3 * r0, false)) : W3);
    }
    #pragma unroll
    for (int d = 0; d < 4; d++) {                // level m = 1024
        float2 a0 = b[4*d], a1 = b[4*d+1], a2 = b[4*d+2], a3 = b[4*d+3];
        dft4_fwd(a0, a1, a2, a3);
        b[4*d]   = a0;
        b[4*d+1] = cmul(a1, W4);
        b[4*d+2] = cmul(a2, W8);
        b[4*d+3] = cmul(a3, W12);
    }
}

// ---- pass 1 (fwd S=1024): gmem float2 loads, paired butterflies j0=2t, j0+1 ----
__device__ __forceinline__ void pass1_fused(float4* z4, const float* __restrict__ xr,
                                            const float* __restrict__ hr, int tid) {
    const float tstep = -6.2831853071795864f / 16384.0f;
    const int j0 = 2 * tid;

    float2 xv[8], hv[8];
    #pragma unroll
    for (int r = 0; r < 8; r++) {
        xv[r] = *(const float2*)(xr + j0 + 1024 * r);
        hv[r] = *(const float2*)(hr + j0 + 1024 * r);
    }

    float2 inA[8], inB[8];
    #pragma unroll
    for (int r = 0; r < 8; r++) {
        inA[r] = make_float2(xv[r].x, hv[r].x);
        inB[r] = make_float2(xv[r].y, hv[r].y);
    }

    float sn, cs;
    float2 bA[16], bB[16];
    __sincosf(tstep * (float)j0, &sn, &cs);
    bfly16_first(inA, bA, make_float2(cs, sn));
    __sincosf(tstep * (float)(j0 + 1), &sn, &cs);
    bfly16_first(inB, bB, make_float2(cs, sn));

    #pragma unroll
    for (int r = 0; r < 16; r++)
        z4[SKEW(j0 + 1024 * r) >> 1] = make_float4(bA[r].x, bA[r].y, bB[r].x, bB[r].y);
}

// ---- middle radix-16 pass (S = 64 or 4), paired butterflies ----
template<int S, bool INV>
__device__ __forceinline__ void pass_mid(float4* z4, int tid) {
    const float ang0 = (INV ? 6.2831853071795864f : -6.2831853071795864f) / (16.0f * (float)S);
    const int idx0 = 2 * tid;
    const int j = idx0 & (S - 1);                // even; pair j, j+1 in same group
    const int base = (idx0 / S) * (16 * S) + j;

    float4 v[16];
    #pragma unroll
    for (int r = 0; r < 16; r++) v[r] = z4[SKEW(base + S * r) >> 1];

    float2 bA[16], bB[16];
    #pragma unroll
    for (int r = 0; r < 16; r++) {
        bA[r] = make_float2(v[r].x, v[r].y);
        bB[r] = make_float2(v[r].z, v[r].w);
    }

    float sn, cs;
    __sincosf(ang0 * (float)j, &sn, &cs);
    bfly16<INV>(bA, make_float2(cs, sn));
    __sincosf(ang0 * (float)(j + 1), &sn, &cs);
    bfly16<INV>(bB, make_float2(cs, sn));

    #pragma unroll
    for (int r = 0; r < 16; r++)
        z4[SKEW(base + S * r) >> 1] = make_float4(bA[r].x, bA[r].y, bB[r].x, bB[r].y);
}

// ---- pass 7 (inv S=1024): Re(outputs 0..8191)*scale to gmem, paired ----
__device__ __forceinline__ void pass7_fused(const float4* z4, float* __restrict__ yr, int tid) {
    const float tstep = 6.2831853071795864f / 16384.0f;
    const float scale = 1.0f / (16384.0f * 16384.0f);
    const int j0 = 2 * tid;

    float4 v[16];
    #pragma unroll
    for (int r = 0; r < 16; r++) v[r] = z4[SKEW(j0 + 1024 * r) >> 1];

    float reA[8], reB[8];
    #pragma unroll
    for (int half = 0; half < 2; half++) {
        float2 b[16];
        #pragma unroll
        for (int r = 0; r < 16; r++)
            b[r] = half ? make_float2(v[r].z, v[r].w) : make_float2(v[r].x, v[r].y);

        float sn, cs;
        __sincosf(tstep * (float)(j0 + half), &sn, &cs);
        const float2 W   = make_float2(cs, sn);
        const float2 W2  = cmul(W, W);
        const float2 W3  = cmul(W2, W);
        const float2 W4  = cmul(W2, W2);
        const float2 W8  = cmul(W4, W4);
        const float2 W12 = cmul(W8, W4);

        #pragma unroll
        for (int d = 0; d < 4; d++) {            // level m = 1024 (full complex)
            float2 a0 = b[4*d];
            float2 a1 = cmul(b[4*d+1], W4);
            float2 a2 = cmul(b[4*d+2], W8);
            float2 a3 = cmul(b[4*d+3], W12);
            dft4_inv(a0, a1, a2, a3);
            b[4*d] = a0; b[4*d+1] = a1; b[4*d+2] = a2; b[4*d+3] = a3;
        }
        float* re = half ? reB : reA;
        #pragma unroll
        for (int r0 = 0; r0 < 4; r0++) {         // level m = 4096: Re of outs only
            float2 in0 = b[r0];
            float2 in1 = cmul(b[r0 + 4],  r0 ? cmul(W,  om16(r0,     true)) : W);
            float  in2x;
            {
                float2 w = r0 ? cmul(W2, om16(2 * r0, true)) : W2;
                float2 vv = b[r0 + 8];
                in2x = fmaf(vv.x, w.x, -vv.y * w.y);    // Re(v * w)
            }
            float2 in3 = cmul(b[r0 + 12], r0 ? cmul(W3, om16(3 * r0, true)) : W3);
            re[r0]     = ((in0.x + in2x) + (in1.x + in3.x)) * scale;  // Re(out[r0])
            re[r0 + 4] = ((in0.x - in2x) - (in1.y - in3.y)) * scale;  // Re(out[r0+4])
        }
    }
    #pragma unroll
    for (int r = 0; r < 8; r++)
        *(float2*)(yr + j0 + 1024 * r) = make_float2(reA[r], reB[r]);
}

// ---- fused middle: R9's verbatim divergent version (known-good; ~10% of time) ----
__device__ __forceinline__ void fused_mid(float2* z, int tid) {
    for (int c = tid; c < N_FFT / 4; c += NT) {
        if (c == 0) {
            float2 A0 = z[SKEW(0)], A1 = z[SKEW(1)], A2 = z[SKEW(2)], A3 = z[SKEW(3)];
            dft4_fwd(A0, A1, A2, A3);            // freqs 0, 4096, 8192, 12288
            float2 Y0 = make_float2(A0.x * A0.y, 0.0f);       // DC: both real
            float2 Y2 = make_float2(A2.x * A2.y, 0.0f);       // Nyquist: both real
            float2 Za = A1, Zb = A3;                           // 4096 <-> 12288
            float2 X = make_float2(0.5f * (Za.x + Zb.x), 0.5f * (Za.y - Zb.y));
            float2 H = make_float2(0.5f * (Za.y + Zb.y), 0.5f * (Zb.x - Za.x));
            float2 Y1 = cmul(X, H);
            float2 Y3 = cconj(Y1);
            dft4_inv(Y0, Y1, Y2, Y3);
            z[SKEW(0)] = Y0; z[SKEW(1)] = Y1; z[SKEW(2)] = Y2; z[SKEW(3)] = Y3;
            continue;
        }
        const int k0 = rev6_base4(c);
        const int cp = rev6_base4(4096 - k0);
        if (c > cp) continue;                    // partner thread handles it (c==cp: self)

        float2 A[4], B[4];
        #pragma unroll
        for (int t = 0; t < 4; t++) A[t] = z[SKEW(4 * c + t)];
        #pragma unroll
        for (int t = 0; t < 4; t++) B[t] = z[SKEW(4 * cp + t)];

        dft4_fwd(A[0], A[1], A[2], A[3]);
        dft4_fwd(B[0], B[1], B[2], B[3]);

        float2 An[4], Bn[4];
        #pragma unroll
        for (int t = 0; t < 4; t++) {
            float2 Za = A[t], Zb = B[3 - t];
            float2 X = make_float2(0.5f * (Za.x + Zb.x), 0.5f * (Za.y - Zb.y));
            float2 H = make_float2(0.5f * (Za.y + Zb.y), 0.5f * (Zb.x - Za.x));
            float2 Y = cmul(X, H);
            An[t] = Y;
            Bn[3 - t] = cconj(Y);
        }

        dft4_inv(An[0], An[1], An[2], An[3]);
        dft4_inv(Bn[0], Bn[1], Bn[2], Bn[3]);

        #pragma unroll
        for (int t = 0; t < 4; t++) z[SKEW(4 * c + t)] = An[t];
        #pragma unroll
        for (int t = 0; t < 4; t++) z[SKEW(4 * cp + t)] = Bn[t];
    }
}

__global__ __launch_bounds__(NT, 1)
void fftconv_kernel(const float* __restrict__ x, const float* __restrict__ h,
                    float* __restrict__ y) {
    extern __shared__ float2 z[];
    float4* z4 = (float4*)z;
    const int row = blockIdx.x;
    const int tid = threadIdx.x;
    const float* xr = x + (size_t)row * L_SIG;
    const float* hr = h + (size_t)row * L_SIG;
    float* yr = y + (size_t)row * L_SIG;

    pass1_fused(z4, xr, hr, tid);       __syncthreads();
    pass_mid<64, false>(z4, tid);       __syncthreads();
    pass_mid<4,  false>(z4, tid);       __syncthreads();
    fused_mid(z, tid);                  __syncthreads();
    pass_mid<4,  true >(z4, tid);       __syncthreads();
    pass_mid<64, true >(z4, tid);       __syncthreads();
    pass7_fused(z4, yr, tid);
}

extern "C" void kernel_launch(void* const* d_in, const int* in_sizes, int n_in,
                              void* d_out, int out_size) {
    const float* x = (const float*)d_in[0];
    const float* h = (const float*)d_in[1];
    float* y = (float*)d_out;

    cudaFuncSetAttribute(fftconv_kernel,
                         cudaFuncAttributeMaxDynamicSharedMemorySize, SMEM_BYTES);

    const int B = in_sizes[0] / L_SIG;   // 4096 rows
    fftconv_kernel<<<B, NT, SMEM_BYTES>>>(x, h, y);
}

// round 17
// speedup vs baseline: 2.2547x; 1.1131x over previous
#include <cuda_runtime.h>

// FFT long conv, N = 16384 = 4^7, one CTA per row.
// R16 = R15 with the scale double-count fixed (R15 produced exactly 2x output).
// Identity: Z = FFT(x + i*h); X[k]H[k] = (Z[k]^2 - conj(Z[N-k])^2)/(4i).
// Define u = -0.5i*Z^2 (pointwise) = 2*U_true; then y = Re(IFFT(u))/N^2
// (the conj term folds into Re; the 2x is already inside u). Middle pass =
// fwd dft4 (m=1, twiddle-free) + pointwise square + inv dft4. No rev6 scatter,
// no divergence, no DC/Nyquist special case.

#define L_SIG  8192
#define N_FFT  16384
#define NT     512
#define SMEM_F2 (N_FFT + (N_FFT >> 4))     // 17408 float2
#define SMEM_BYTES (SMEM_F2 * 8)           // 139264 B

__device__ __forceinline__ int SKEW(int i) { return i + (i >> 4); }

__device__ __forceinline__ float2 cadd(float2 a, float2 b) { return make_float2(a.x + b.x, a.y + b.y); }
__device__ __forceinline__ float2 csub(float2 a, float2 b) { return make_float2(a.x - b.x, a.y - b.y); }
__device__ __forceinline__ float2 cmul(float2 a, float2 b) {
    return make_float2(fmaf(a.x, b.x, -a.y * b.y), fmaf(a.x, b.y, a.y * b.x));
}

__device__ __forceinline__ void dft4_fwd(float2& a0, float2& a1, float2& a2, float2& a3) {
    float2 t0 = cadd(a0, a2), t1 = csub(a0, a2), t2 = cadd(a1, a3), t3 = csub(a1, a3);
    a0 = cadd(t0, t2); a2 = csub(t0, t2);
    a1 = make_float2(t1.x + t3.y, t1.y - t3.x);   // t1 - i*t3
    a3 = make_float2(t1.x - t3.y, t1.y + t3.x);   // t1 + i*t3
}
__device__ __forceinline__ void dft4_inv(float2& a0, float2& a1, float2& a2, float2& a3) {
    float2 t0 = cadd(a0, a2), t1 = csub(a0, a2), t2 = cadd(a1, a3), t3 = csub(a1, a3);
    a0 = cadd(t0, t2); a2 = csub(t0, t2);
    a1 = make_float2(t1.x - t3.y, t1.y + t3.x);   // t1 + i*t3
    a3 = make_float2(t1.x + t3.y, t1.y - t3.x);   // t1 - i*t3
}

// u = -0.5i * z^2 with z = a + ib:  u = (a*b, 0.5*(b^2 - a^2)).
// u == 2*U_true, so the downstream output scale is exactly 1/N^2 (no extra 2).
__device__ __forceinline__ float2 sqmid(float2 v) {
    return make_float2(v.x * v.y, 0.5f * fmaf(v.y, v.y, -v.x * v.x));
}

// omega16^k = e^{-+ 2*pi*i*k/16}; k compile-time after unroll (k in {0..9})
__device__ __forceinline__ float2 om16(int k, bool inv) {
    const float OC[10] = {1.f, 0.9238795325f, 0.7071067812f, 0.3826834324f, 0.f,
                          0.f, -0.7071067812f, 0.f, 0.f, -0.9238795325f};
    const float OS[10] = {0.f, 0.3826834324f, 0.7071067812f, 0.9238795325f, 1.f,
                          0.f, 0.7071067812f, 0.f, 0.f, -0.3826834324f};
    return make_float2(OC[k], inv ? OS[k] : -OS[k]);
}

// ---- fused forward pass, S=1024, reads x,h from gmem (upper half implicit zero) ----
__device__ __forceinline__ void pass1_fused(float2* z, const float* __restrict__ xr,
                                            const float* __restrict__ hr, int tid) {
    const float tstep = -6.2831853071795864f / 16384.0f;
    #pragma unroll
    for (int it = 0; it < 2; it++) {
        const int j = tid + it * NT;

        float2 in[8];
        #pragma unroll
        for (int r = 0; r < 8; r++)
            in[r] = make_float2(xr[j + 1024 * r], hr[j + 1024 * r]);

        float sn, cs;
        __sincosf(tstep * (float)j, &sn, &cs);
        const float2 W   = make_float2(cs, sn);
        const float2 W2  = cmul(W, W);
        const float2 W3  = cmul(W2, W);
        const float2 W4  = cmul(W2, W2);
        const float2 W8  = cmul(W4, W4);
        const float2 W12 = cmul(W8, W4);

        float2 b[16];
        #pragma unroll
        for (int r0 = 0; r0 < 4; r0++) {         // level m = 4096, a2=a3=0
            float2 a0 = in[r0], a1 = in[r0 + 4];
            float2 y0 = cadd(a0, a1);
            float2 y2 = csub(a0, a1);
            float2 y1 = make_float2(a0.x + a1.y, a0.y - a1.x);  // a0 - i*a1
            float2 y3 = make_float2(a0.x - a1.y, a0.y + a1.x);  // a0 + i*a1
            b[r0]      = y0;
            b[r0 + 4]  = cmul(y1, r0 ? cmul(W,  om16(r0,     false)) : W);
            b[r0 + 8]  = cmul(y2, r0 ? cmul(W2, om16(2 * r0, false)) : W2);
            b[r0 + 12] = cmul(y3, r0 ? cmul(W3, om16(3 * r0, false)) : W3);
        }
        #pragma unroll
        for (int d = 0; d < 4; d++) {            // level m = 1024
            float2 a0 = b[4*d], a1 = b[4*d+1], a2 = b[4*d+2], a3 = b[4*d+3];
            dft4_fwd(a0, a1, a2, a3);
            b[4*d]   = a0;
            b[4*d+1] = cmul(a1, W4);
            b[4*d+2] = cmul(a2, W8);
            b[4*d+3] = cmul(a3, W12);
        }
        #pragma unroll
        for (int r = 0; r < 16; r++) z[SKEW(j + 1024 * r)] = b[r];
    }
}

// ---- fused inverse pass, S=1024, writes Re(outputs 0..8191)*scale to gmem ----
__device__ __forceinline__ void pass7_fused(const float2* z, float* __restrict__ yr, int tid) {
    const float tstep = 6.2831853071795864f / 16384.0f;
    // y = Re(IFFT(u)) / N^2  (u = -0.5i*Z^2 already carries the conj-fold 2x)
    const float scale = 1.0f / (16384.0f * 16384.0f);
    #pragma unroll
    for (int it = 0; it < 2; it++) {
        const int j = tid + it * NT;

        float2 b[16];
        #pragma unroll
        for (int r = 0; r < 16; r++) b[r] = z[SKEW(j + 1024 * r)];

        float sn, cs;
        __sincosf(tstep * (float)j, &sn, &cs);
        const float2 W   = make_float2(cs, sn);
        const float2 W2  = cmul(W, W);
        const float2 W3  = cmul(W2, W);
        const float2 W4  = cmul(W2, W2);
        const float2 W8  = cmul(W4, W4);
        const float2 W12 = cmul(W8, W4);

        #pragma unroll
        for (int d = 0; d < 4; d++) {            // level m = 1024 (full complex)
            float2 a0 = b[4*d];
            float2 a1 = cmul(b[4*d+1], W4);
            float2 a2 = cmul(b[4*d+2], W8);
            float2 a3 = cmul(b[4*d+3], W12);
            dft4_inv(a0, a1, a2, a3);
            b[4*d] = a0; b[4*d+1] = a1; b[4*d+2] = a2; b[4*d+3] = a3;
        }
        #pragma unroll
        for (int r0 = 0; r0 < 4; r0++) {         // level m = 4096: Re of outs 0..7 only
            float2 in0 = b[r0];
            float2 in1 = cmul(b[r0 + 4],  r0 ? cmul(W,  om16(r0,     true)) : W);
            float  in2x;
            {
                float2 w = r0 ? cmul(W2, om16(2 * r0, true)) : W2;
                float2 v = b[r0 + 8];
                in2x = fmaf(v.x, w.x, -v.y * w.y);      // Re(v * w)
            }
            float2 in3 = cmul(b[r0 + 12], r0 ? cmul(W3, om16(3 * r0, true)) : W3);
            float re0 = (in0.x + in2x) + (in1.x + in3.x);   // Re(out[r0])
            float re1 = (in0.x - in2x) - (in1.y - in3.y);   // Re(out[r0+4])
            yr[j + 1024 * r0]       = re0 * scale;
            yr[j + 1024 * (r0 + 4)] = re1 * scale;
        }
    }
}

// ---- generic radix-16 pass (middle passes: S=64, S=4), sincosf twiddles ----
template<int S, bool INV>
__device__ __forceinline__ void radix16_pass(float2* z, int tid) {
    const float ang0 = (INV ? 6.2831853071795864f : -6.2831853071795864f) / (16.0f * (float)S);
    #pragma unroll
    for (int it = 0; it < (N_FFT / 16) / NT; it++) {
        const int idx = tid + it * NT;
        const int j = idx & (S - 1);
        const int base = (idx / S) * (16 * S) + j;

        float2 b[16];
        #pragma unroll
        for (int r = 0; r < 16; r++) b[r] = z[SKEW(base + S * r)];

        float sn, cs;
        __sincosf(ang0 * (float)j, &sn, &cs);
        const float2 W   = make_float2(cs, sn);
        const float2 W2  = cmul(W, W);
        const float2 W3  = cmul(W2, W);
        const float2 W4  = cmul(W2, W2);
        const float2 W8  = cmul(W4, W4);
        const float2 W12 = cmul(W8, W4);

        if (!INV) {
            #pragma unroll
            for (int r0 = 0; r0 < 4; r0++) {     // level m = 4S
                float2 a0 = b[r0], a1 = b[r0 + 4], a2 = b[r0 + 8], a3 = b[r0 + 12];
                dft4_fwd(a0, a1, a2, a3);
                b[r0]      = a0;
                b[r0 + 4]  = cmul(a1, r0 ? cmul(W,  om16(r0,     false)) : W);
                b[r0 + 8]  = cmul(a2, r0 ? cmul(W2, om16(2 * r0, false)) : W2);
                b[r0 + 12] = cmul(a3, r0 ? cmul(W3, om16(3 * r0, false)) : W3);
            }
            #pragma unroll
            for (int d = 0; d < 4; d++) {        // level m = S
                float2 a0 = b[4*d], a1 = b[4*d+1], a2 = b[4*d+2], a3 = b[4*d+3];
                dft4_fwd(a0, a1, a2, a3);
                b[4*d]   = a0;
                b[4*d+1] = cmul(a1, W4);
                b[4*d+2] = cmul(a2, W8);
                b[4*d+3] = cmul(a3, W12);
            }
        } else {
            #pragma unroll
            for (int d = 0; d < 4; d++) {        // level m = S
                float2 a0 = b[4*d];
                float2 a1 = cmul(b[4*d+1], W4);
                float2 a2 = cmul(b[4*d+2], W8);
                float2 a3 = cmul(b[4*d+3], W12);
                dft4_inv(a0, a1, a2, a3);
                b[4*d] = a0; b[4*d+1] = a1; b[4*d+2] = a2; b[4*d+3] = a3;
            }
            #pragma unroll
            for (int r0 = 0; r0 < 4; r0++) {     // level m = 4S
                float2 a0 = b[r0];
                float2 a1 = cmul(b[r0 + 4],  r0 ? cmul(W,  om16(r0,     true)) : W);
                float2 a2 = cmul(b[r0 + 8],  r0 ? cmul(W2, om16(2 * r0, true)) : W2);
                float2 a3 = cmul(b[r0 + 12], r0 ? cmul(W3, om16(3 * r0, true)) : W3);
                dft4_inv(a0, a1, a2, a3);
                b[r0] = a0; b[r0 + 4] = a1; b[r0 + 8] = a2; b[r0 + 12] = a3;
            }
        }

        #pragma unroll
        for (int r = 0; r < 16; r++) z[SKEW(base + S * r)] = b[r];
    }
}

// ---- middle: fwd dft4 (m=1, twiddle-free) + pointwise square + inv dft4 ----
// Quads strided by NT: lane-adjacent quads -> conflict-free on the skew.
// Uniform for all k (incl. DC/Nyquist). Tiny live state; runtime loop.
__device__ __forceinline__ void mid_square(float2* z, int tid) {
    #pragma unroll 1
    for (int it = 0; it < (N_FFT / 4) / NT; it++) {
        const int q = tid + it * NT;
        float2 a0 = z[SKEW(4 * q + 0)];
        float2 a1 = z[SKEW(4 * q + 1)];
        float2 a2 = z[SKEW(4 * q + 2)];
        float2 a3 = z[SKEW(4 * q + 3)];
        dft4_fwd(a0, a1, a2, a3);
        a0 = sqmid(a0); a1 = sqmid(a1); a2 = sqmid(a2); a3 = sqmid(a3);
        dft4_inv(a0, a1, a2, a3);
        z[SKEW(4 * q + 0)] = a0;
        z[SKEW(4 * q + 1)] = a1;
        z[SKEW(4 * q + 2)] = a2;
        z[SKEW(4 * q + 3)] = a3;
    }
}

__global__ __launch_bounds__(NT, 1)
void fftconv_kernel(const float* __restrict__ x, const float* __restrict__ h,
                    float* __restrict__ y) {
    extern __shared__ float2 z[];
    const int row = blockIdx.x;
    const int tid = threadIdx.x;
    const float* xr = x + (size_t)row * L_SIG;
    const float* hr = h + (size_t)row * L_SIG;
    float* yr = y + (size_t)row * L_SIG;

    pass1_fused(z, xr, hr, tid);       __syncthreads();
    radix16_pass<64, false>(z, tid);   __syncthreads();
    radix16_pass<4,  false>(z, tid);   __syncthreads();
    mid_square(z, tid);                __syncthreads();
    radix16_pass<4,  true >(z, tid);   __syncthreads();
    radix16_pass<64, true >(z, tid);   __syncthreads();
    pass7_fused(z, yr, tid);
}

extern "C" void kernel_launch(void* const* d_in, const int* in_sizes, int n_in,
                              void* d_out, int out_size) {
    const float* x = (const float*)d_in[0];
    const float* h = (const float*)d_in[1];
    float* y = (float*)d_out;

    cudaFuncSetAttribute(fftconv_kernel,
                         cudaFuncAttributeMaxDynamicSharedMemorySize, SMEM_BYTES);

    const int B = in_sizes[0] / L_SIG;   // 4096 rows
    fftconv_kernel<<<B, NT, SMEM_BYTES>>>(x, h, y);
}